// round 12
// baseline (speedup 1.0000x reference)
#include <cuda_runtime.h>
#include <cstdint>

#define OBS_DIM 256
#define POP_DIM 10
#define NIN     (OBS_DIM * POP_DIM)   // 2560
#define HID1    256
#define HID2    256
#define OUTP    80                    // ACT_DIM * DE_POP
#define ACT_DIM 8
#define DE_POP  10
#define T       25
#define ENC_VTH 0.999f
#define CHUNK   128
#define NTHR    128                   // threads per CTA; each owns 2 columns

// ---------------- scratch: transposed weights ----------------
__device__ float g_W1T[NIN  * HID1];
__device__ float g_W2T[HID1 * HID2];
__device__ float g_W3T[HID2 * OUTP];

__global__ void k_t1(const float* __restrict__ w1) {
    int idx = blockIdx.x * blockDim.x + threadIdx.x;
    if (idx < HID1 * NIN) { int h = idx / NIN, j = idx - h * NIN; g_W1T[j * HID1 + h] = w1[idx]; }
}
__global__ void k_t2(const float* __restrict__ w2) {
    int idx = blockIdx.x * blockDim.x + threadIdx.x;
    if (idx < HID2 * HID1) { int h = idx / HID1, j = idx - h * HID1; g_W2T[j * HID2 + h] = w2[idx]; }
}
__global__ void k_t3(const float* __restrict__ w3) {
    int idx = blockIdx.x * blockDim.x + threadIdx.x;
    if (idx < OUTP * HID2) { int o = idx / HID2, j = idx - o * HID2; g_W3T[j * OUTP + o] = w3[idx]; }
}

// ---------------- helpers ----------------

__device__ __forceinline__ unsigned long long pack2(float w) {
    unsigned long long r;
    asm("mov.b64 %0, {%1, %1};" : "=l"(r) : "f"(w));
    return r;
}
__device__ __forceinline__ void unpack2(unsigned long long v, float* lo, float* hi) {
    asm("mov.b64 {%0, %1}, %2;" : "=f"(*lo), "=f"(*hi) : "l"(v));
}

// exclusive block scan over 128 threads
__device__ __forceinline__ int block_excl_scan(int val, int tid, int* s_warp, int* total_out)
{
    const int lane = tid & 31, wid = tid >> 5;
    int x = val;
#pragma unroll
    for (int o = 1; o < 32; o <<= 1) {
        int y = __shfl_up_sync(0xffffffffu, x, o);
        if (lane >= o) x += y;
    }
    __syncthreads();                 // also protects reuse of s_idx/s_msk
    if (lane == 31) s_warp[wid] = x;
    __syncthreads();
    int woff = 0, tot = 0;
#pragma unroll
    for (int i = 0; i < 4; ++i) {
        int v = s_warp[i];
        tot += v;
        if (i < wid) woff += v;
    }
    *total_out = tot;
    return woff + (x - val);
}

// 25-step LIF with dynamic threshold -> 25-bit spike mask (scalar, per column)
__device__ __forceinline__ unsigned lif25(const float* acc, float bias)
{
    float c = 0.f, v = 0.f, s = 0.f;
    unsigned m = 0u;
#pragma unroll
    for (int t = 0; t < T; ++t) {
        c = c * 0.5f + acc[t] + bias;
        const float vn  = v * 0.75f * (1.0f - s) + c;
        const float vth = 0.25f + 0.5f * (expf((v - vn) * (1.0f / 3.0f)) - 1.0f);
        s = (vn > vth) ? 1.0f : 0.0f;
        v = vn;
        if (s != 0.0f) m |= (1u << t);
    }
    return m;
}

// accx/accy: 13 packed f32x2 accumulators per column, lanes = (t, t+1).
// bits row read as ulonglong2 (4 floats = lanes for 2 packed FMAs). Bit-exact
// lane-wise vs scalar fmaf; per-column entry order unchanged.
__device__ __forceinline__ void accum2(unsigned long long accx[13], unsigned long long accy[13],
                                       unsigned long long wx, unsigned long long wy,
                                       const float* __restrict__ row)
{
    const ulonglong2* bp = reinterpret_cast<const ulonglong2*>(row);   // rows 16B-aligned
#pragma unroll
    for (int i = 0; i < 6; ++i) {
        const ulonglong2 bb = bp[i];                  // LDS.128 broadcast: t = 4i .. 4i+3
        asm("fma.rn.f32x2 %0, %1, %2, %0;" : "+l"(accx[2*i])     : "l"(wx), "l"(bb.x));
        asm("fma.rn.f32x2 %0, %1, %2, %0;" : "+l"(accx[2*i + 1]) : "l"(wx), "l"(bb.y));
        asm("fma.rn.f32x2 %0, %1, %2, %0;" : "+l"(accy[2*i])     : "l"(wy), "l"(bb.x));
        asm("fma.rn.f32x2 %0, %1, %2, %0;" : "+l"(accy[2*i + 1]) : "l"(wy), "l"(bb.y));
    }
    const ulonglong2 bb = bp[6];                      // t = 24,25 (25..27 are zero pad)
    asm("fma.rn.f32x2 %0, %1, %2, %0;" : "+l"(accx[12]) : "l"(wx), "l"(bb.x));
    asm("fma.rn.f32x2 %0, %1, %2, %0;" : "+l"(accy[12]) : "l"(wy), "l"(bb.x));
}

// sequential paired gather: thread serves cols (colbase, colbase+1), walks the FULL
// entry list in order. ALL threads must call (contains barriers); 'active' gates math.
__device__ __forceinline__ void gather2(
    const float* __restrict__ W, int stride, int colbase, bool active,
    int total,
    const unsigned short* __restrict__ s_idx,
    const unsigned*       __restrict__ s_msk,
    float (*s_bits)[28], int tid,
    unsigned long long accx[13], unsigned long long accy[13])
{
#pragma unroll
    for (int i = 0; i < 13; ++i) { accx[i] = 0ull; accy[i] = 0ull; }

    for (int cs = 0; cs < total; cs += CHUNK) {
        const int n = min(CHUNK, total - cs);
        if (tid < n) {                                 // build float-bit rows (vector STS)
            const unsigned m = s_msk[cs + tid];
            float4* rp = reinterpret_cast<float4*>(s_bits[tid]);
#pragma unroll
            for (int i = 0; i < 7; ++i) {
                float4 v;
                v.x = (4*i + 0 < T) ? (float)((m >> (4*i + 0)) & 1u) : 0.0f;
                v.y = (4*i + 1 < T) ? (float)((m >> (4*i + 1)) & 1u) : 0.0f;
                v.z = (4*i + 2 < T) ? (float)((m >> (4*i + 2)) & 1u) : 0.0f;
                v.w = (4*i + 3 < T) ? (float)((m >> (4*i + 3)) & 1u) : 0.0f;
                rp[i] = v;
            }
        }
        __syncthreads();

        if (active) {
            int k = 0;
            for (; k + 1 < n; k += 2) {               // 2-deep LDG pipeline, order preserved
                const int j0 = (int)s_idx[cs + k];          // scalar ushort loads only
                const int j1 = (int)s_idx[cs + k + 1];
                const float2 w0 = *reinterpret_cast<const float2*>(W + j0 * stride + colbase);
                const float2 w1 = *reinterpret_cast<const float2*>(W + j1 * stride + colbase);
                accum2(accx, accy, pack2(w0.x), pack2(w0.y), s_bits[k]);
                accum2(accx, accy, pack2(w1.x), pack2(w1.y), s_bits[k + 1]);
            }
            if (k < n) {
                const int j = (int)s_idx[cs + k];
                const float2 w = *reinterpret_cast<const float2*>(W + j * stride + colbase);
                accum2(accx, accy, pack2(w.x), pack2(w.y), s_bits[k]);
            }
        }
        __syncthreads();
    }
}

// unpack 13 packed accumulators into 26 floats (acc[25] = pad)
__device__ __forceinline__ void unpack_acc(const unsigned long long a[13], float out[26])
{
#pragma unroll
    for (int i = 0; i < 13; ++i) unpack2(a[i], &out[2*i], &out[2*i + 1]);
}

// ---------------- fused SNN forward: 1 CTA (128 thr) per batch row ----------------
__global__ void __launch_bounds__(NTHR)
k_snn(const float* __restrict__ obs,
      const float* __restrict__ enc_mean,
      const float* __restrict__ enc_std,
      const float* __restrict__ b1,
      const float* __restrict__ b2,
      const float* __restrict__ b3,
      const float* __restrict__ dec_w,
      const float* __restrict__ dec_b,
      float* __restrict__ out)
{
    const int b   = blockIdx.x;
    const int tid = threadIdx.x;

    __shared__ unsigned short s_idx[NIN];
    __shared__ unsigned int   s_msk[NIN];
    __shared__ __align__(16) float s_bits[CHUNK][28];
    __shared__ int   s_warp[4];
    __shared__ float s_pop[OUTP];

    // ===== population encoder: thread t owns obs dims 2t, 2t+1 (j order preserved) =====
    unsigned pm[2 * POP_DIM];
    int myCount = 0;
#pragma unroll
    for (int d = 0; d < 2; ++d) {
        const float o = obs[b * OBS_DIM + 2 * tid + d];
#pragma unroll
        for (int p = 0; p < POP_DIM; ++p) {
            const int j    = (2 * tid + d) * POP_DIM + p;
            const float m  = enc_mean[j];
            const float sd = enc_std[j];
            const float dd = o - m;
            const float a  = expf((-0.5f * (dd * dd)) / (sd * sd));
            float volt = 0.0f;
            unsigned mask = 0u;
#pragma unroll
            for (int t = 0; t < T; ++t) {
                volt += a;
                if (volt > ENC_VTH) { mask |= (1u << t); volt -= ENC_VTH; }
            }
            pm[d * POP_DIM + p] = mask;
            myCount += (mask != 0u);
        }
    }

    int total0;
    int ofs = block_excl_scan(myCount, tid, s_warp, &total0);
#pragma unroll
    for (int q = 0; q < 2 * POP_DIM; ++q) {
        if (pm[q]) {
            s_idx[ofs] = (unsigned short)(tid * 2 * POP_DIM + q);
            s_msk[ofs] = pm[q];
            ++ofs;
        }
    }
    __syncthreads();

    const int colbase = 2 * tid;
    unsigned long long accx[13], accy[13];
    float af[26];
    unsigned m0, m1;

    // ===== layer 1 =====
    gather2(g_W1T, HID1, colbase, true, total0, s_idx, s_msk, s_bits, tid, accx, accy);
    unpack_acc(accx, af); m0 = lif25(af, b1[colbase]);
    unpack_acc(accy, af); m1 = lif25(af, b1[colbase + 1]);

    int tot1;
    int o1 = block_excl_scan((m0 ? 1 : 0) + (m1 ? 1 : 0), tid, s_warp, &tot1);
    if (m0) { s_idx[o1] = (unsigned short)colbase;       s_msk[o1] = m0; ++o1; }
    if (m1) { s_idx[o1] = (unsigned short)(colbase + 1); s_msk[o1] = m1; }
    __syncthreads();

    // ===== layer 2 =====
    gather2(g_W2T, HID2, colbase, true, tot1, s_idx, s_msk, s_bits, tid, accx, accy);
    unpack_acc(accx, af); m0 = lif25(af, b2[colbase]);
    unpack_acc(accy, af); m1 = lif25(af, b2[colbase + 1]);

    int tot2;
    int o2 = block_excl_scan((m0 ? 1 : 0) + (m1 ? 1 : 0), tid, s_warp, &tot2);
    if (m0) { s_idx[o2] = (unsigned short)colbase;       s_msk[o2] = m0; ++o2; }
    if (m1) { s_idx[o2] = (unsigned short)(colbase + 1); s_msk[o2] = m1; }
    __syncthreads();

    // ===== layer 3: threads 0..39, cols (2t, 2t+1), sequential entries =====
    const bool l3 = (tid < OUTP / 2);
    gather2(g_W3T, OUTP, colbase, l3, tot2, s_idx, s_msk, s_bits, tid, accx, accy);
    if (l3) {
        unpack_acc(accx, af); m0 = lif25(af, b3[colbase]);
        unpack_acc(accy, af); m1 = lif25(af, b3[colbase + 1]);
        s_pop[colbase]     = (float)__popc(m0) * (1.0f / 25.0f);
        s_pop[colbase + 1] = (float)__popc(m1) * (1.0f / 25.0f);
    }
    __syncthreads();

    // ===== decoder =====
    if (tid < ACT_DIM) {
        float raw = 0.0f;
#pragma unroll
        for (int p = 0; p < DE_POP; ++p)
            raw += s_pop[tid * DE_POP + p] * dec_w[tid * DE_POP + p];
        raw += dec_b[tid];
        out[b * ACT_DIM + tid] = tanhf(raw);
    }
}

// ---------------- launch ----------------
extern "C" void kernel_launch(void* const* d_in, const int* in_sizes, int n_in,
                              void* d_out, int out_size)
{
    const float* obs      = (const float*)d_in[0];
    const float* enc_mean = (const float*)d_in[1];
    const float* enc_std  = (const float*)d_in[2];
    const float* w1       = (const float*)d_in[3];
    const float* b1       = (const float*)d_in[4];
    const float* w2       = (const float*)d_in[5];
    const float* b2       = (const float*)d_in[6];
    const float* w3       = (const float*)d_in[7];
    const float* b3       = (const float*)d_in[8];
    const float* dec_w    = (const float*)d_in[9];
    const float* dec_b    = (const float*)d_in[10];

    const int B = in_sizes[0] / OBS_DIM;

    k_t1<<<(HID1 * NIN  + 255) / 256, 256>>>(w1);
    k_t2<<<(HID1 * HID2 + 255) / 256, 256>>>(w2);
    k_t3<<<(OUTP * HID2 + 255) / 256, 256>>>(w3);
    k_snn<<<B, NTHR>>>(obs, enc_mean, enc_std, b1, b2, b3, dec_w, dec_b, (float*)d_out);
}

// round 13
// speedup vs baseline: 1.1007x; 1.1007x over previous
#include <cuda_runtime.h>
#include <cstdint>

#define OBS_DIM 256
#define POP_DIM 10
#define NIN     (OBS_DIM * POP_DIM)   // 2560
#define HID1    256
#define HID2    256
#define OUTP    80                    // ACT_DIM * DE_POP
#define ACT_DIM 8
#define DE_POP  10
#define T       25
#define ENC_VTH 0.999f
#define CHUNK   128
#define NTHR    128                   // threads per CTA; each owns 2 columns

// ---------------- scratch: transposed weights ----------------
__device__ float g_W1T[NIN  * HID1];
__device__ float g_W2T[HID1 * HID2];
__device__ float g_W3T[HID2 * OUTP];

__global__ void k_t1(const float* __restrict__ w1) {
    int idx = blockIdx.x * blockDim.x + threadIdx.x;
    if (idx < HID1 * NIN) { int h = idx / NIN, j = idx - h * NIN; g_W1T[j * HID1 + h] = w1[idx]; }
}
__global__ void k_t2(const float* __restrict__ w2) {
    int idx = blockIdx.x * blockDim.x + threadIdx.x;
    if (idx < HID2 * HID1) { int h = idx / HID1, j = idx - h * HID1; g_W2T[j * HID2 + h] = w2[idx]; }
}
__global__ void k_t3(const float* __restrict__ w3) {
    int idx = blockIdx.x * blockDim.x + threadIdx.x;
    if (idx < OUTP * HID2) { int o = idx / HID2, j = idx - o * HID2; g_W3T[j * OUTP + o] = w3[idx]; }
}

// ---------------- helpers ----------------

// exclusive block scan over 128 threads
__device__ __forceinline__ int block_excl_scan(int val, int tid, int* s_warp, int* total_out)
{
    const int lane = tid & 31, wid = tid >> 5;
    int x = val;
#pragma unroll
    for (int o = 1; o < 32; o <<= 1) {
        int y = __shfl_up_sync(0xffffffffu, x, o);
        if (lane >= o) x += y;
    }
    __syncthreads();                 // also protects reuse of s_idx/s_msk
    if (lane == 31) s_warp[wid] = x;
    __syncthreads();
    int woff = 0, tot = 0;
#pragma unroll
    for (int i = 0; i < 4; ++i) {
        int v = s_warp[i];
        tot += v;
        if (i < wid) woff += v;
    }
    *total_out = tot;
    return woff + (x - val);
}

// two independent 25-step LIFs (cols 2t, 2t+1) -> two spike masks
__device__ __forceinline__ void lif25x2(const float2* acc, float2 bias,
                                        unsigned* m0, unsigned* m1)
{
    float c0 = 0.f, v0 = 0.f, s0 = 0.f;
    float c1 = 0.f, v1 = 0.f, s1 = 0.f;
    unsigned r0 = 0u, r1 = 0u;
#pragma unroll
    for (int t = 0; t < T; ++t) {
        c0 = c0 * 0.5f + acc[t].x + bias.x;
        c1 = c1 * 0.5f + acc[t].y + bias.y;
        const float vn0  = v0 * 0.75f * (1.0f - s0) + c0;
        const float vn1  = v1 * 0.75f * (1.0f - s1) + c1;
        const float vth0 = 0.25f + 0.5f * (expf((v0 - vn0) * (1.0f / 3.0f)) - 1.0f);
        const float vth1 = 0.25f + 0.5f * (expf((v1 - vn1) * (1.0f / 3.0f)) - 1.0f);
        s0 = (vn0 > vth0) ? 1.0f : 0.0f;
        s1 = (vn1 > vth1) ? 1.0f : 0.0f;
        v0 = vn0; v1 = vn1;
        if (s0 != 0.0f) r0 |= (1u << t);
        if (s1 != 0.0f) r1 |= (1u << t);
    }
    *m0 = r0; *m1 = r1;
}

// acc[0..24](.x,.y) += (w.x, w.y) * bits_row[t]  (bits in {0,1}; bit-exact predicated add)
// 6 x LDS.128 covers t=0..23; t=24 via one scalar LDS. No pad-lane FFMAs.
__device__ __forceinline__ void accum_pair(float2 acc[T], float2 w,
                                           const float* __restrict__ row)
{
    const float4* bp = reinterpret_cast<const float4*>(row);
#pragma unroll
    for (int i = 0; i < 6; ++i) {
        const float4 bv = bp[i];                       // LDS.128 broadcast
        acc[4*i + 0].x = fmaf(w.x, bv.x, acc[4*i + 0].x);
        acc[4*i + 0].y = fmaf(w.y, bv.x, acc[4*i + 0].y);
        acc[4*i + 1].x = fmaf(w.x, bv.y, acc[4*i + 1].x);
        acc[4*i + 1].y = fmaf(w.y, bv.y, acc[4*i + 1].y);
        acc[4*i + 2].x = fmaf(w.x, bv.z, acc[4*i + 2].x);
        acc[4*i + 2].y = fmaf(w.y, bv.z, acc[4*i + 2].y);
        acc[4*i + 3].x = fmaf(w.x, bv.w, acc[4*i + 3].x);
        acc[4*i + 3].y = fmaf(w.y, bv.w, acc[4*i + 3].y);
    }
    const float b24 = row[24];                         // scalar LDS broadcast
    acc[24].x = fmaf(w.x, b24, acc[24].x);
    acc[24].y = fmaf(w.y, b24, acc[24].y);
}

// sequential paired gather: thread serves cols (colbase, colbase+1), walks the FULL
// entry list in k order (bit-identical per-column sums). 4-deep LDG pipeline.
// ALL threads must call (contains barriers); 'active' gates the math.
__device__ __forceinline__ void gather2(
    const float* __restrict__ W, int stride, int colbase, bool active,
    int total,
    const unsigned short* __restrict__ s_idx,
    const unsigned*       __restrict__ s_msk,
    float (*s_bits)[28], int tid,
    float2 acc[T])
{
#pragma unroll
    for (int i = 0; i < T; ++i) acc[i] = make_float2(0.f, 0.f);

    for (int cs = 0; cs < total; cs += CHUNK) {
        const int n = min(CHUNK, total - cs);
        if (tid < n) {                                 // build float-bit rows (vector STS)
            const unsigned m = s_msk[cs + tid];
            float4* rp = reinterpret_cast<float4*>(s_bits[tid]);
#pragma unroll
            for (int i = 0; i < 7; ++i) {
                float4 v;
                v.x = (4*i + 0 < T) ? (float)((m >> (4*i + 0)) & 1u) : 0.0f;
                v.y = (4*i + 1 < T) ? (float)((m >> (4*i + 1)) & 1u) : 0.0f;
                v.z = (4*i + 2 < T) ? (float)((m >> (4*i + 2)) & 1u) : 0.0f;
                v.w = (4*i + 3 < T) ? (float)((m >> (4*i + 3)) & 1u) : 0.0f;
                rp[i] = v;
            }
        }
        __syncthreads();

        if (active) {
            int k = 0;
            for (; k + 3 < n; k += 4) {               // 4-deep LDG pipeline, k-order accum
                const int j0 = (int)s_idx[cs + k];
                const int j1 = (int)s_idx[cs + k + 1];
                const int j2 = (int)s_idx[cs + k + 2];
                const int j3 = (int)s_idx[cs + k + 3];
                const float2 w0 = *reinterpret_cast<const float2*>(W + j0 * stride + colbase);
                const float2 w1 = *reinterpret_cast<const float2*>(W + j1 * stride + colbase);
                const float2 w2 = *reinterpret_cast<const float2*>(W + j2 * stride + colbase);
                const float2 w3 = *reinterpret_cast<const float2*>(W + j3 * stride + colbase);
                accum_pair(acc, w0, s_bits[k]);
                accum_pair(acc, w1, s_bits[k + 1]);
                accum_pair(acc, w2, s_bits[k + 2]);
                accum_pair(acc, w3, s_bits[k + 3]);
            }
            for (; k < n; ++k) {
                const int j = (int)s_idx[cs + k];
                const float2 w = *reinterpret_cast<const float2*>(W + j * stride + colbase);
                accum_pair(acc, w, s_bits[k]);
            }
        }
        __syncthreads();
    }
}

// ---------------- fused SNN forward: 1 CTA (128 thr) per batch row ----------------
__global__ void __launch_bounds__(NTHR, 6)
k_snn(const float* __restrict__ obs,
      const float* __restrict__ enc_mean,
      const float* __restrict__ enc_std,
      const float* __restrict__ b1,
      const float* __restrict__ b2,
      const float* __restrict__ b3,
      const float* __restrict__ dec_w,
      const float* __restrict__ dec_b,
      float* __restrict__ out)
{
    const int b   = blockIdx.x;
    const int tid = threadIdx.x;

    __shared__ unsigned short s_idx[NIN];
    __shared__ unsigned int   s_msk[NIN];
    __shared__ __align__(16) float s_bits[CHUNK][28];
    __shared__ int   s_warp[4];
    __shared__ float s_pop[OUTP];

    // ===== population encoder: thread t owns obs dims 2t, 2t+1 (j order preserved) =====
    unsigned pm[2 * POP_DIM];
    int myCount = 0;
#pragma unroll
    for (int d = 0; d < 2; ++d) {
        const float o = obs[b * OBS_DIM + 2 * tid + d];
#pragma unroll
        for (int p = 0; p < POP_DIM; ++p) {
            const int j    = (2 * tid + d) * POP_DIM + p;
            const float m  = enc_mean[j];
            const float sd = enc_std[j];
            const float dd = o - m;
            const float a  = expf((-0.5f * (dd * dd)) / (sd * sd));
            float volt = 0.0f;
            unsigned mask = 0u;
#pragma unroll
            for (int t = 0; t < T; ++t) {
                volt += a;
                if (volt > ENC_VTH) { mask |= (1u << t); volt -= ENC_VTH; }
            }
            pm[d * POP_DIM + p] = mask;
            myCount += (mask != 0u);
        }
    }

    int total0;
    int ofs = block_excl_scan(myCount, tid, s_warp, &total0);
#pragma unroll
    for (int q = 0; q < 2 * POP_DIM; ++q) {
        if (pm[q]) {
            s_idx[ofs] = (unsigned short)(tid * 2 * POP_DIM + q);
            s_msk[ofs] = pm[q];
            ++ofs;
        }
    }
    __syncthreads();

    const int colbase = 2 * tid;
    float2 acc[T];
    unsigned m0, m1;

    // ===== layer 1 (cols 2t, 2t+1; sequential entries) =====
    gather2(g_W1T, HID1, colbase, true, total0, s_idx, s_msk, s_bits, tid, acc);
    {
        const float2 bias = *reinterpret_cast<const float2*>(b1 + colbase);
        lif25x2(acc, bias, &m0, &m1);
    }
    int tot1;
    int o1 = block_excl_scan((m0 ? 1 : 0) + (m1 ? 1 : 0), tid, s_warp, &tot1);
    if (m0) { s_idx[o1] = (unsigned short)colbase;       s_msk[o1] = m0; ++o1; }
    if (m1) { s_idx[o1] = (unsigned short)(colbase + 1); s_msk[o1] = m1; }
    __syncthreads();

    // ===== layer 2 =====
    gather2(g_W2T, HID2, colbase, true, tot1, s_idx, s_msk, s_bits, tid, acc);
    {
        const float2 bias = *reinterpret_cast<const float2*>(b2 + colbase);
        lif25x2(acc, bias, &m0, &m1);
    }
    int tot2;
    int o2 = block_excl_scan((m0 ? 1 : 0) + (m1 ? 1 : 0), tid, s_warp, &tot2);
    if (m0) { s_idx[o2] = (unsigned short)colbase;       s_msk[o2] = m0; ++o2; }
    if (m1) { s_idx[o2] = (unsigned short)(colbase + 1); s_msk[o2] = m1; }
    __syncthreads();

    // ===== layer 3: threads 0..39, cols (2t, 2t+1), sequential entries =====
    const bool l3 = (tid < OUTP / 2);
    gather2(g_W3T, OUTP, colbase, l3, tot2, s_idx, s_msk, s_bits, tid, acc);
    if (l3) {
        const float2 bias = *reinterpret_cast<const float2*>(b3 + colbase);
        lif25x2(acc, bias, &m0, &m1);
        s_pop[colbase]     = (float)__popc(m0) * (1.0f / 25.0f);
        s_pop[colbase + 1] = (float)__popc(m1) * (1.0f / 25.0f);
    }
    __syncthreads();

    // ===== decoder =====
    if (tid < ACT_DIM) {
        float raw = 0.0f;
#pragma unroll
        for (int p = 0; p < DE_POP; ++p)
            raw += s_pop[tid * DE_POP + p] * dec_w[tid * DE_POP + p];
        raw += dec_b[tid];
        out[b * ACT_DIM + tid] = tanhf(raw);
    }
}

// ---------------- launch ----------------
extern "C" void kernel_launch(void* const* d_in, const int* in_sizes, int n_in,
                              void* d_out, int out_size)
{
    const float* obs      = (const float*)d_in[0];
    const float* enc_mean = (const float*)d_in[1];
    const float* enc_std  = (const float*)d_in[2];
    const float* w1       = (const float*)d_in[3];
    const float* b1       = (const float*)d_in[4];
    const float* w2       = (const float*)d_in[5];
    const float* b2       = (const float*)d_in[6];
    const float* w3       = (const float*)d_in[7];
    const float* b3       = (const float*)d_in[8];
    const float* dec_w    = (const float*)d_in[9];
    const float* dec_b    = (const float*)d_in[10];

    const int B = in_sizes[0] / OBS_DIM;

    k_t1<<<(HID1 * NIN  + 255) / 256, 256>>>(w1);
    k_t2<<<(HID1 * HID2 + 255) / 256, 256>>>(w2);
    k_t3<<<(OUTP * HID2 + 255) / 256, 256>>>(w3);
    k_snn<<<B, NTHR>>>(obs, enc_mean, enc_std, b1, b2, b3, dec_w, dec_b, (float*)d_out);
}